// round 1
// baseline (speedup 1.0000x reference)
#include <cuda_runtime.h>

#define BATCH 8
#define CC    64
#define CQ    8
#define NN_   4096
#define TM    128   // m positions per block (1 thread per m)
#define TN    128   // n tile size

// Scratch (device globals; no allocation allowed)
__device__ float g_f[(size_t)BATCH * NN_ * CQ];   // f transposed: [B][N][8]
__device__ float g_g[(size_t)BATCH * NN_ * CQ];   // g transposed: [B][N][8]
__device__ float g_h[(size_t)BATCH * NN_ * CC];   // h transposed: [B][N][64]

// ---- packed f32x2 helpers (sm_100+ PTX) ----
__device__ __forceinline__ unsigned long long pack2(float a, float b) {
    unsigned long long r;
    asm("mov.b64 %0, {%1, %2};" : "=l"(r) : "f"(a), "f"(b));
    return r;
}
__device__ __forceinline__ void unpack2(unsigned long long v, float& a, float& b) {
    asm("mov.b64 {%0, %1}, %2;" : "=f"(a), "=f"(b) : "l"(v));
}
__device__ __forceinline__ unsigned long long ffma2(unsigned long long a,
                                                    unsigned long long b,
                                                    unsigned long long c) {
    unsigned long long d;
    asm("fma.rn.f32x2 %0, %1, %2, %3;" : "=l"(d) : "l"(a), "l"(b), "l"(c));
    return d;
}

// ============================================================================
// Kernel 1: 1x1-conv projections. x:[B,64,N] -> f,g:[B,N,8], h:[B,N,64]
// ============================================================================
__global__ __launch_bounds__(TM) void proj_kernel(
    const float* __restrict__ x,
    const float* __restrict__ Wq, const float* __restrict__ bq,
    const float* __restrict__ Wk, const float* __restrict__ bk,
    const float* __restrict__ Wv, const float* __restrict__ bv)
{
    __shared__ float sWq[CQ * CC], sWk[CQ * CC], sWv[CC * CC];
    __shared__ float sbq[CQ], sbk[CQ], sbv[CC];
    int t = threadIdx.x;
    for (int i = t; i < CQ * CC; i += TM) { sWq[i] = Wq[i]; sWk[i] = Wk[i]; }
    for (int i = t; i < CC * CC; i += TM) sWv[i] = Wv[i];
    if (t < CQ) { sbq[t] = bq[t]; sbk[t] = bk[t]; }
    if (t < CC) sbv[t] = bv[t];
    __syncthreads();

    int b = blockIdx.x / (NN_ / TM);
    int n = (blockIdx.x % (NN_ / TM)) * TM + t;

    // load x[b, :, n] into registers (coalesced per channel)
    float xv[CC];
    const float* xb = x + ((size_t)b * CC) * NN_ + n;
    #pragma unroll
    for (int c = 0; c < CC; c++) xv[c] = xb[(size_t)c * NN_];

    size_t base = (size_t)b * NN_ + n;

    #pragma unroll 2
    for (int d = 0; d < CQ; d++) {
        float af = sbq[d], ag = sbk[d];
        #pragma unroll
        for (int c = 0; c < CC; c++) {
            af = fmaf(sWq[d * CC + c], xv[c], af);
            ag = fmaf(sWk[d * CC + c], xv[c], ag);
        }
        g_f[base * CQ + d] = af;
        g_g[base * CQ + d] = ag;
    }
    #pragma unroll 4
    for (int o = 0; o < CC; o++) {
        float a = sbv[o];
        #pragma unroll
        for (int c = 0; c < CC; c++) a = fmaf(sWv[o * CC + c], xv[c], a);
        g_h[base * CC + o] = a;
    }
}

// ============================================================================
// Kernel 2: fused flash attention. 1 thread per output position m.
//  sweep 1: row max of scores s(n) = f[:,n] . q   (q pre-scaled by log2e)
//  sweep 2: w = exp2(s - mx); l += w; acc += w * h[:,n]   (packed f32x2 FMA)
//  epilogue: out[:,m] = gamma * acc / l + x[:,m]
// ============================================================================
__global__ __launch_bounds__(TM) void attn_kernel(
    const float* __restrict__ x,
    const float* __restrict__ gamma,
    float* __restrict__ out)
{
    __shared__ __align__(16) float f_s[TN * CQ];   // [nn][8]   4 KB
    __shared__ __align__(16) float h_s[TN * CC];   // [nn][64] 32 KB

    int t = threadIdx.x;
    int b = blockIdx.x / (NN_ / TM);
    int m = (blockIdx.x % (NN_ / TM)) * TM + t;

    const float LOG2E = 1.4426950408889634f;
    float q[CQ];
    {
        const float* gp = g_g + ((size_t)b * NN_ + m) * CQ;
        #pragma unroll
        for (int d = 0; d < CQ; d++) q[d] = gp[d] * LOG2E;
    }
    const float* fb = g_f + (size_t)b * NN_ * CQ;
    const float* hb = g_h + (size_t)b * NN_ * CC;

    // ---- sweep 1: max ----
    float mx = -3.0e38f;
    for (int n0 = 0; n0 < NN_; n0 += TN) {
        const float4* src = (const float4*)(fb + (size_t)n0 * CQ);
        float4* dst = (float4*)f_s;
        dst[t]        = src[t];
        dst[t + TM]   = src[t + TM];
        __syncthreads();
        #pragma unroll 4
        for (int nn = 0; nn < TN; nn++) {
            const float* fr = f_s + nn * CQ;
            float s = q[0] * fr[0];
            #pragma unroll
            for (int d = 1; d < CQ; d++) s = fmaf(q[d], fr[d], s);
            mx = fmaxf(mx, s);
        }
        __syncthreads();
    }

    // ---- sweep 2: exp-weighted accumulation ----
    unsigned long long acc[CC / 2];
    #pragma unroll
    for (int i = 0; i < CC / 2; i++) acc[i] = 0ULL;
    float l = 0.0f;

    for (int n0 = 0; n0 < NN_; n0 += TN) {
        const float4* src = (const float4*)(fb + (size_t)n0 * CQ);
        float4* dst = (float4*)f_s;
        dst[t]      = src[t];
        dst[t + TM] = src[t + TM];
        const float4* hsrc = (const float4*)(hb + (size_t)n0 * CC);
        float4* hdst = (float4*)h_s;
        #pragma unroll
        for (int i = 0; i < (TN * CC / 4) / TM; i++)   // 16 float4 per thread
            hdst[t + i * TM] = hsrc[t + i * TM];
        __syncthreads();

        #pragma unroll 2
        for (int nn = 0; nn < TN; nn++) {
            const float* fr = f_s + nn * CQ;
            float s = q[0] * fr[0];
            #pragma unroll
            for (int d = 1; d < CQ; d++) s = fmaf(q[d], fr[d], s);
            float w = exp2f(s - mx);
            l += w;
            unsigned long long wp = pack2(w, w);
            const ulonglong2* hr = (const ulonglong2*)(h_s + nn * CC);
            #pragma unroll
            for (int i = 0; i < CC / 4; i++) {       // 16 x 16B loads -> 32 FFMA2
                ulonglong2 hv = hr[i];
                acc[2 * i]     = ffma2(hv.x, wp, acc[2 * i]);
                acc[2 * i + 1] = ffma2(hv.y, wp, acc[2 * i + 1]);
            }
        }
        __syncthreads();
    }

    // ---- epilogue: out = gamma * acc / l + x ----
    float scale = gamma[0] / l;
    const float* xb = x   + ((size_t)b * CC) * NN_ + m;
    float*       ob = out + ((size_t)b * CC) * NN_ + m;
    #pragma unroll
    for (int i = 0; i < CC / 2; i++) {
        float lo, hi;
        unpack2(acc[i], lo, hi);
        ob[(size_t)(2 * i) * NN_]     = fmaf(lo, scale, xb[(size_t)(2 * i) * NN_]);
        ob[(size_t)(2 * i + 1) * NN_] = fmaf(hi, scale, xb[(size_t)(2 * i + 1) * NN_]);
    }
}

// ============================================================================
extern "C" void kernel_launch(void* const* d_in, const int* in_sizes, int n_in,
                              void* d_out, int out_size)
{
    const float* x     = (const float*)d_in[0];
    const float* Wq    = (const float*)d_in[1];
    const float* bq    = (const float*)d_in[2];
    const float* Wk    = (const float*)d_in[3];
    const float* bk    = (const float*)d_in[4];
    const float* Wv    = (const float*)d_in[5];
    const float* bv    = (const float*)d_in[6];
    const float* gamma = (const float*)d_in[7];
    float* out = (float*)d_out;

    int nblk = BATCH * NN_ / TM;   // 256
    proj_kernel<<<nblk, TM>>>(x, Wq, bq, Wk, bk, Wv, bv);
    attn_kernel<<<nblk, TM>>>(x, gamma, out);
}